// round 6
// baseline (speedup 1.0000x reference)
#include <cuda_runtime.h>
#include <math.h>

// Problem dims
#define C_   3
#define T_   100
#define B_   512
#define F_   128
#define HX_  128
#define HZ_  128
#define H_   256
#define EH_  128
#define L_   64

#define NB_   86   // CTAs per channel (86*6=516 >= 512; 258 CTAs = 1 wave @ 2/SM)
#define RMAX_ 6    // rows per CTA

// ---- big activations scratch ----
__device__ float g_PEq[(size_t)C_ * T_ * B_ * L_];  // x_phi@Weq + beq  (feeds z)
__device__ float g_PI[(size_t)C_ * T_ * B_ * H_];   // x_phi@Wih_x + bih+bhh+bihz
__device__ float g_Hs[(size_t)C_ * T_ * B_ * H_];   // h at step input
__device__ float g_Zs[(size_t)C_ * T_ * B_ * L_];   // z per step

// ---- folded weights (computed on-device each run; tiny) ----
__device__ float g_Weq[C_ * HX_ * L_];    // We_x @ Wqm            [128,64]/ch
__device__ float g_beq[C_ * L_];          // be@Wqm + bqm
__device__ float g_Wcomb[C_ * H_ * L_];   // We_h @ Wqm            [256,64]/ch
__device__ float g_Wihz[L_ * H_];         // Wzp @ Wih_z           [64,256]
__device__ float g_bihz[H_];              // bzp @ Wih_z
__device__ float g_Wdz[C_ * L_ * EH_];    // Wzp @ Wd_z            [64,128]/ch
__device__ float g_bdz[C_ * EH_];         // bzp@Wd_z + bd
__device__ float g_Wzo[C_ * L_ * F_];     // Wdz @ Wpm             [64,128]/ch
__device__ float g_Who[C_ * H_ * F_];     // Wd_h @ Wpm            [256,128]/ch
__device__ float g_bo[C_ * F_];           // bdz@Wpm + bpm

// ===========================================================================
// small generic GEMM for weight folding (one CTA per task, K=128 always)
// ===========================================================================
__device__ __forceinline__ void small_gemm(const float* __restrict__ A, int lda,
                                           const float* __restrict__ Bm, int ldb,
                                           float* __restrict__ out, int M, int N,
                                           const float* __restrict__ addv) {
    for (int idx = threadIdx.x; idx < M * N; idx += 256) {
        const int m = idx / N, n = idx % N;
        float s = addv ? addv[n] : 0.f;
        const float* a = A + (size_t)m * lda;
        const float* b = Bm + n;
#pragma unroll 4
        for (int k = 0; k < 128; ++k) s = fmaf(a[k], b[(size_t)k * ldb], s);
        out[idx] = s;
    }
}

// fold stage 1: products of raw inputs (29 CTAs)
__global__ void __launch_bounds__(256) kernelF1(
    const float* __restrict__ We, const float* __restrict__ be,
    const float* __restrict__ Wqm, const float* __restrict__ bqm,
    const float* __restrict__ Wzp, const float* __restrict__ bzp,
    const float* __restrict__ Wd, const float* __restrict__ bd,
    const float* __restrict__ Wih) {
    const int t = blockIdx.x;
    if (t < 6) {                       // Weq blocks (M=64)
        const int c = t >> 1, rb = t & 1;
        small_gemm(We + (size_t)c * 384 * EH_ + rb * 64 * EH_, EH_,
                   Wqm + (size_t)c * EH_ * L_, L_,
                   g_Weq + c * HX_ * L_ + rb * 64 * L_, 64, L_, nullptr);
    } else if (t < 18) {               // Wcomb blocks
        const int u = t - 6, c = u >> 2, rb = u & 3;
        small_gemm(We + (size_t)c * 384 * EH_ + (128 + rb * 64) * EH_, EH_,
                   Wqm + (size_t)c * EH_ * L_, L_,
                   g_Wcomb + c * H_ * L_ + rb * 64 * L_, 64, L_, nullptr);
    } else if (t < 21) {               // Wdz = Wzp @ Wd_z
        const int c = t - 18;
        small_gemm(Wzp, HZ_, Wd + (size_t)c * 384 * EH_, EH_,
                   g_Wdz + c * L_ * EH_, L_, EH_, nullptr);
    } else if (t == 21) {              // Wihz = Wzp @ Wih_z
        small_gemm(Wzp, HZ_, Wih + 128 * H_, H_, g_Wihz, L_, H_, nullptr);
    } else if (t < 25) {               // beq = be@Wqm + bqm
        const int c = t - 22;
        small_gemm(be + c * EH_, EH_, Wqm + (size_t)c * EH_ * L_, L_,
                   g_beq + c * L_, 1, L_, bqm + c * L_);
    } else if (t < 28) {               // bdz = bzp@Wd_z + bd
        const int c = t - 25;
        small_gemm(bzp, HZ_, Wd + (size_t)c * 384 * EH_, EH_,
                   g_bdz + c * EH_, 1, EH_, bd + c * EH_);
    } else {                           // bihz = bzp@Wih_z
        small_gemm(bzp, HZ_, Wih + 128 * H_, H_, g_bihz, 1, H_, nullptr);
    }
}

// fold stage 2: products involving fold-1 outputs (18 CTAs)
__global__ void __launch_bounds__(256) kernelF2(
    const float* __restrict__ Wd, const float* __restrict__ Wpm,
    const float* __restrict__ bpm) {
    const int t = blockIdx.x;
    if (t < 3) {                       // Wzo = Wdz @ Wpm
        const int c = t;
        small_gemm(g_Wdz + c * L_ * EH_, EH_, Wpm + (size_t)c * EH_ * F_, F_,
                   g_Wzo + c * L_ * F_, L_, F_, nullptr);
    } else if (t < 15) {               // Who = Wd_h @ Wpm
        const int u = t - 3, c = u >> 2, rb = u & 3;
        small_gemm(Wd + (size_t)c * 384 * EH_ + (128 + rb * 64) * EH_, EH_,
                   Wpm + (size_t)c * EH_ * F_, F_,
                   g_Who + c * H_ * F_ + rb * 64 * F_, 64, F_, nullptr);
    } else {                           // bo = bdz@Wpm + bpm
        const int c = t - 15;
        small_gemm(g_bdz + c * EH_, EH_, Wpm + (size_t)c * EH_ * F_, F_,
                   g_bo + c * F_, 1, F_, bpm + c * F_);
    }
}

// ===========================================================================
// Parallel GEMM machinery (kernels A and C)
// ===========================================================================
__device__ __forceinline__ void gemm64(const float* __restrict__ As,
                                       const float* __restrict__ Ws,
                                       int k0, float acc[8][8]) {
    const int tc = threadIdx.x & 15;
    const int tr = threadIdx.x >> 4;
    const float* ap = As + tr * 8 * 128 + k0;
    const float* bp = Ws + tc * 8;
#pragma unroll 4
    for (int k = 0; k < 64; ++k) {
        const float4 b0 = *reinterpret_cast<const float4*>(bp + k * 128);
        const float4 b1 = *reinterpret_cast<const float4*>(bp + k * 128 + 4);
        float a[8];
#pragma unroll
        for (int i = 0; i < 8; ++i) a[i] = ap[i * 128 + k];
        const float bv[8] = {b0.x, b0.y, b0.z, b0.w, b1.x, b1.y, b1.z, b1.w};
#pragma unroll
        for (int i = 0; i < 8; ++i)
#pragma unroll
            for (int j = 0; j < 8; ++j)
                acc[i][j] = fmaf(a[i], bv[j], acc[i][j]);
    }
}

// K=128, N=64 gemm: thread = 4 rows x 8 cols (tr=tid>>3 in 0..31, tc=tid&7)
__device__ __forceinline__ void gemm_K128_N64(const float* __restrict__ As,
                                              const float* __restrict__ Ws,
                                              float acc[4][8]) {
    const int tc = threadIdx.x & 7;
    const int tr = threadIdx.x >> 3;
    const float* ap = As + tr * 4 * 128;
    const float* bp = Ws + tc * 8;
#pragma unroll 4
    for (int k = 0; k < 128; ++k) {
        const float4 b0 = *reinterpret_cast<const float4*>(bp + k * 64);
        const float4 b1 = *reinterpret_cast<const float4*>(bp + k * 64 + 4);
        float a[4];
#pragma unroll
        for (int i = 0; i < 4; ++i) a[i] = ap[i * 128 + k];
        const float bv[8] = {b0.x, b0.y, b0.z, b0.w, b1.x, b1.y, b1.z, b1.w};
#pragma unroll
        for (int i = 0; i < 4; ++i)
#pragma unroll
            for (int j = 0; j < 8; ++j)
                acc[i][j] = fmaf(a[i], bv[j], acc[i][j]);
    }
}

// Load a 128x128 fp32 tile (row stride ld) into smem
__device__ __forceinline__ void load_tile(float* dst, const float* __restrict__ src,
                                          int ld) {
    for (int idx = threadIdx.x; idx < 128 * 32; idx += 256) {
        const int r = idx >> 5;
        const int c4 = idx & 31;
        reinterpret_cast<float4*>(dst)[(r << 5) + c4] =
            *reinterpret_cast<const float4*>(src + (size_t)r * ld + (c4 << 2));
    }
}

// Load a 128x64 tile (contiguous rows of 64) into cols 0..63 of As (stride 128)
__device__ __forceinline__ void load_tile64(float* dst, const float* __restrict__ src) {
    for (int idx = threadIdx.x; idx < 128 * 16; idx += 256) {
        const int r = idx >> 4;
        const int c4 = idx & 15;
        reinterpret_cast<float4*>(dst)[(r << 5) + c4] =
            *reinterpret_cast<const float4*>(src + (size_t)r * 64 + (c4 << 2));
    }
}

// Load a 64x128 fp32 slab (row stride ld) into smem
__device__ __forceinline__ void load_half(float* dst, const float* __restrict__ src,
                                          int ld) {
    for (int idx = threadIdx.x; idx < 64 * 32; idx += 256) {
        const int r = idx >> 5;
        const int c4 = idx & 31;
        reinterpret_cast<float4*>(dst)[(r << 5) + c4] =
            *reinterpret_cast<const float4*>(src + (size_t)r * ld + (c4 << 2));
    }
}

// linear copy of 8192 floats (e.g. full [128,64] or [64,128] weight)
__device__ __forceinline__ void load_lin8k(float* dst, const float* __restrict__ src) {
    for (int idx = threadIdx.x; idx < 2048; idx += 256)
        reinterpret_cast<float4*>(dst)[idx] =
            reinterpret_cast<const float4*>(src)[idx];
}

__device__ __forceinline__ void zero_acc(float acc[8][8]) {
#pragma unroll
    for (int i = 0; i < 8; ++i)
#pragma unroll
        for (int j = 0; j < 8; ++j) acc[i][j] = 0.f;
}

// full 128-deep GEMM as two 64-row slabs streamed through Ws
__device__ __forceinline__ void gemm128_slabs(const float* As, float* Ws,
                                              const float* __restrict__ W,
                                              int ldw, float acc[8][8]) {
#pragma unroll
    for (int h = 0; h < 2; ++h) {
        load_half(Ws, W + (size_t)(h * 64) * ldw, ldw);
        __syncthreads();
        gemm64(As, Ws, h * 64, acc);
        __syncthreads();
    }
}

// ---------------------------------------------------------------------------
// Kernel A: x_phi = x@Wx+bx; PEq = x_phi@Weq + beq;
//           PI = x_phi@Wih_x + bih + bhh + bihz
// grid (4 btiles, T, C), 256 threads, 96KB dynamic smem
// ---------------------------------------------------------------------------
__global__ void __launch_bounds__(256, 2) kernelA(
    const float* __restrict__ x, const float* __restrict__ Wx,
    const float* __restrict__ bx, const float* __restrict__ Wih,
    const float* __restrict__ bih, const float* __restrict__ bhh) {
    extern __shared__ float sm[];
    float* As = sm;                // 128x128
    float* Ws = sm + 128 * 128;    // 8192-float slab
    const int bt = blockIdx.x, t = blockIdx.y, c = blockIdx.z;
    const long rg0 = ((long)(c * T_ + t) * B_ + bt * 128);
    const int tc = threadIdx.x & 15, tr = threadIdx.x >> 4;

    load_tile(As, x + rg0 * F_, F_);

    float acc[8][8];
    zero_acc(acc);
    gemm128_slabs(As, Ws, Wx + (size_t)c * F_ * HX_, HX_, acc);  // x_phi

    // write x_phi (+bx) back into As (trailing sync above protects reads)
#pragma unroll
    for (int i = 0; i < 8; ++i)
#pragma unroll
        for (int j = 0; j < 8; ++j)
            As[(tr * 8 + i) * 128 + tc * 8 + j] = acc[i][j] + bx[c * HX_ + tc * 8 + j];

    // PEq = x_phi @ Weq + beq  (N=64)
    load_lin8k(Ws, g_Weq + c * HX_ * L_);
    __syncthreads();
    {
        float acc4[4][8];
#pragma unroll
        for (int i = 0; i < 4; ++i)
#pragma unroll
            for (int j = 0; j < 8; ++j) acc4[i][j] = 0.f;
        gemm_K128_N64(As, Ws, acc4);
        const int qc = threadIdx.x & 7, qr = threadIdx.x >> 3;
#pragma unroll
        for (int i = 0; i < 4; ++i)
#pragma unroll
            for (int j = 0; j < 8; ++j)
                g_PEq[(rg0 + qr * 4 + i) * L_ + qc * 8 + j] =
                    acc4[i][j] + g_beq[c * L_ + qc * 8 + j];
    }
    __syncthreads();  // protect Ws before PI slabs

    // PI = x_phi @ Wih_x + bih + bhh + bihz (two 128-col halves)
#pragma unroll
    for (int half = 0; half < 2; ++half) {
        zero_acc(acc);
        gemm128_slabs(As, Ws, Wih + half * 128, H_, acc);
#pragma unroll
        for (int i = 0; i < 8; ++i)
#pragma unroll
            for (int j = 0; j < 8; ++j) {
                const int n = half * 128 + tc * 8 + j;
                g_PI[(rg0 + tr * 8 + i) * H_ + n] =
                    acc[i][j] + bih[n] + bhh[n] + g_bihz[n];
            }
    }
}

// ===========================================================================
// Kernel B: the recurrence (2 stages per step), TRUE 2 CTAs/SM (<=128 regs).
// ===========================================================================
template <int K, int N>
__device__ __forceinline__ void mm4(const float* __restrict__ Wg,
                                    const float* __restrict__ a_s,
                                    float4 acc[RMAX_]) {
    constexpr int G = N / 4;      // thread groups (one per 4 columns)
    constexpr int P = 256 / G;    // k partitions
    constexpr int Ks = K / P;
    const int g = threadIdx.x % G;
    const int p = threadIdx.x / G;
    const float4* wp = reinterpret_cast<const float4*>(Wg) + (size_t)(p * Ks) * G + g;
    const float* ap = a_s + p * Ks;

    // 2-deep weight double-buffer (16 transient regs, fits 128-reg cap)
    float4 w0 = wp[0 * G], w1 = wp[1 * G];
#pragma unroll 1
    for (int k = 0; k < Ks; k += 2) {
        float4 n0, n1;
        if (k + 2 < Ks) {
            n0 = wp[(k + 2) * G];
            n1 = wp[(k + 3) * G];
        }
#pragma unroll
        for (int r = 0; r < RMAX_; ++r) {
            const float2 a = *reinterpret_cast<const float2*>(ap + r * K + k);
            acc[r].x = fmaf(a.x, w0.x, acc[r].x);
            acc[r].y = fmaf(a.x, w0.y, acc[r].y);
            acc[r].z = fmaf(a.x, w0.z, acc[r].z);
            acc[r].w = fmaf(a.x, w0.w, acc[r].w);
            acc[r].x = fmaf(a.y, w1.x, acc[r].x);
            acc[r].y = fmaf(a.y, w1.y, acc[r].y);
            acc[r].z = fmaf(a.y, w1.z, acc[r].z);
            acc[r].w = fmaf(a.y, w1.w, acc[r].w);
        }
        w0 = n0; w1 = n1;
    }
}

template <int N>
__device__ __forceinline__ void store_scr(float* __restrict__ scr,
                                          const float4 acc[RMAX_]) {
    const int g = threadIdx.x % (N / 4);
    const int p = threadIdx.x / (N / 4);
#pragma unroll
    for (int r = 0; r < RMAX_; ++r)
        *reinterpret_cast<float4*>(scr + (size_t)(p * RMAX_ + r) * N + 4 * g) = acc[r];
}

__device__ __forceinline__ void zero4(float4 acc[RMAX_]) {
#pragma unroll
    for (int r = 0; r < RMAX_; ++r) acc[r] = make_float4(0.f, 0.f, 0.f, 0.f);
}

__global__ void __launch_bounds__(256, 2) kernelB(
    const float* __restrict__ Whh, const float* __restrict__ h0) {
    __shared__ __align__(16) float hs[RMAX_ * H_];                 // 6 KB
    __shared__ __align__(16) float zs[RMAX_ * L_];                 // 1.5 KB
    __shared__ __align__(16) float scr[16 * RMAX_ * 64];           // 24 KB (P*N=1024)

    const int c = blockIdx.y;
    // overlapping coverage: 86 CTAs x 6 rows = 516 >= 512; duplicated rows
    // compute bit-identical values, duplicate global stores are benign.
    const int r0 = (blockIdx.x * (B_ - RMAX_)) / (NB_ - 1);
    const int tid = threadIdx.x;

    for (int idx = tid; idx < RMAX_ * H_; idx += 256)
        hs[idx] = h0[(size_t)(c * B_ + r0) * H_ + idx];
    __syncthreads();

    const float* Wcomb = g_Wcomb + c * H_ * L_;
    float4 acc[RMAX_];

    long rg0 = (long)c * T_ * B_ + r0;
    for (int t = 0; t < T_; ++t, rg0 += B_) {
        // prefetch this step's PEq and PI into registers (overlaps with FMA
        // blocks below; scoreboard binds only at epilogue use)
        float pe0 = g_PEq[rg0 * L_ + tid];
        float pe1 = (tid < RMAX_ * L_ - 256) ? g_PEq[rg0 * L_ + 256 + tid] : 0.f;
        float pip[RMAX_];
#pragma unroll
        for (int j = 0; j < RMAX_; ++j)
            pip[j] = g_PI[rg0 * H_ + j * 256 + tid];

        // ---- S1: z = PEq + h @ Wcomb   (K=256, N=64, P=16)
        zero4(acc);
        mm4<256, 64>(Wcomb, hs, acc);
        store_scr<64>(scr, acc);
        // store Hs[t] = h (pre-update) while partials land
        for (int idx = tid; idx < RMAX_ * H_; idx += 256)
            g_Hs[rg0 * H_ + idx] = hs[idx];
        __syncthreads();
#pragma unroll
        for (int u = 0; u < 2; ++u) {   // RMAX_*L_ = 384 outputs
            const int idx = u * 256 + tid;
            if (idx < RMAX_ * L_) {
                const int r = idx >> 6, n = idx & 63;
                float s = u == 0 ? pe0 : pe1;
#pragma unroll
                for (int p = 0; p < 16; ++p)
                    s += scr[(size_t)(p * RMAX_ + r) * 64 + n];
                zs[idx] = s;
                g_Zs[rg0 * L_ + idx] = s;
            }
        }
        __syncthreads();

        // ---- S2: h' = tanh(PI + z@Wihz + h@Whh)   (N=256, P=4)
        zero4(acc);
        mm4<64, 256>(g_Wihz, zs, acc);
        mm4<256, 256>(Whh, hs, acc);
        store_scr<256>(scr, acc);
        __syncthreads();
#pragma unroll
        for (int j = 0; j < RMAX_; ++j) {   // RMAX_*H_ = 1536 outputs
            const int idx = j * 256 + tid;
            const int r = idx >> 8, n = idx & 255;
            float s = pip[j];
#pragma unroll
            for (int p = 0; p < 4; ++p)
                s += scr[(size_t)(p * RMAX_ + r) * 256 + n];
            hs[idx] = tanhf(s);
        }
        __syncthreads();
    }
}

// ---------------------------------------------------------------------------
// Kernel C: out = Zs@Wzo + Hs@Who + bo
// grid (4 btiles, T, C), 256 threads, 96KB dynamic smem
// ---------------------------------------------------------------------------
__global__ void __launch_bounds__(256, 2) kernelC(float* __restrict__ out) {
    extern __shared__ float sm[];
    float* As = sm;
    float* Ws = sm + 128 * 128;
    const int bt = blockIdx.x, t = blockIdx.y, c = blockIdx.z;
    const long rg0 = ((long)(c * T_ + t) * B_ + bt * 128);
    const int tc = threadIdx.x & 15, tr = threadIdx.x >> 4;

    float acc[8][8];
    zero_acc(acc);

    // h part: two 128-row slices of Who (K=256 total)
    load_tile(As, g_Hs + rg0 * H_, H_);
    gemm128_slabs(As, Ws, g_Who + (size_t)c * H_ * F_, F_, acc);
    load_tile(As, g_Hs + rg0 * H_ + 128, H_);
    gemm128_slabs(As, Ws, g_Who + (size_t)c * H_ * F_ + 128 * F_, F_, acc);

    // z part: K=64
    load_tile64(As, g_Zs + rg0 * L_);
    load_lin8k(Ws, g_Wzo + c * L_ * F_);   // [64,128]
    __syncthreads();
    gemm64(As, Ws, 0, acc);

#pragma unroll
    for (int i = 0; i < 8; ++i)
#pragma unroll
        for (int j = 0; j < 8; ++j)
            out[(rg0 + tr * 8 + i) * F_ + tc * 8 + j] =
                acc[i][j] + g_bo[c * F_ + tc * 8 + j];
}

// ---------------------------------------------------------------------------
extern "C" void kernel_launch(void* const* d_in, const int* in_sizes, int n_in,
                              void* d_out, int out_size) {
    (void)in_sizes; (void)n_in; (void)out_size;
    const float* x        = (const float*)d_in[0];
    const float* phi_x_W  = (const float*)d_in[1];
    const float* phi_x_b  = (const float*)d_in[2];
    const float* enc_W    = (const float*)d_in[3];
    const float* enc_b    = (const float*)d_in[4];
    const float* enc_mu_W = (const float*)d_in[5];
    const float* enc_mu_b = (const float*)d_in[6];
    const float* phi_z_W  = (const float*)d_in[7];
    const float* phi_z_b  = (const float*)d_in[8];
    const float* dec_W    = (const float*)d_in[9];
    const float* dec_b    = (const float*)d_in[10];
    const float* dec_mu_W = (const float*)d_in[11];
    const float* dec_mu_b = (const float*)d_in[12];
    const float* rnn_Wih  = (const float*)d_in[13];
    const float* rnn_Whh  = (const float*)d_in[14];
    const float* rnn_bih  = (const float*)d_in[15];
    const float* rnn_bhh  = (const float*)d_in[16];
    const float* h0       = (const float*)d_in[17];
    float* out = (float*)d_out;

    const size_t smem = (128 * 128 + 64 * 128) * sizeof(float);  // 96 KB
    cudaFuncSetAttribute(kernelA, cudaFuncAttributeMaxDynamicSharedMemorySize, (int)smem);
    cudaFuncSetAttribute(kernelC, cudaFuncAttributeMaxDynamicSharedMemorySize, (int)smem);

    kernelF1<<<29, 256>>>(enc_W, enc_b, enc_mu_W, enc_mu_b, phi_z_W, phi_z_b,
                          dec_W, dec_b, rnn_Wih);
    kernelF2<<<18, 256>>>(dec_W, dec_mu_W, dec_mu_b);
    kernelA<<<dim3(4, T_, C_), 256, smem>>>(x, phi_x_W, phi_x_b,
                                            rnn_Wih, rnn_bih, rnn_bhh);
    kernelB<<<dim3(NB_, C_), 256>>>(rnn_Whh, h0);
    kernelC<<<dim3(4, T_, C_), 256, smem>>>(out);
}

// round 7
// speedup vs baseline: 1.3333x; 1.3333x over previous
#include <cuda_runtime.h>
#include <math.h>

// Problem dims
#define C_   3
#define T_   100
#define B_   512
#define F_   128
#define HX_  128
#define HZ_  128
#define H_   256
#define EH_  128
#define L_   64

#define NB_   86   // CTAs per channel (86*6=516 >= 512; 258 CTAs, 1 wave @ 2/SM)
#define RMAX_ 6    // rows per CTA

// ---- big activations scratch ----
__device__ float g_PEq[(size_t)C_ * T_ * B_ * L_];  // x_phi@Weq + beq  (feeds z)
__device__ float g_PI[(size_t)C_ * T_ * B_ * H_];   // x_phi@Wihq + bihq
__device__ float g_Hs[(size_t)C_ * T_ * B_ * H_];   // h at step input
__device__ float g_Zs[(size_t)C_ * T_ * B_ * L_];   // z per step

// ---- folded weights (computed on-device each run; tiny) ----
__device__ float g_Weq[C_ * HX_ * L_];    // We_x @ Wqm              [128,64]/ch
__device__ float g_beq[C_ * L_];          // be@Wqm + bqm
__device__ float g_Wcomb[C_ * H_ * L_];   // We_h @ Wqm              [256,64]/ch
__device__ float g_Wihz[L_ * H_];         // Wzp @ Wih_z             [64,256]
__device__ float g_bihz[H_];              // bzp @ Wih_z
__device__ float g_Wdz[C_ * L_ * EH_];    // Wzp @ Wd_z              [64,128]/ch
__device__ float g_bdz[C_ * EH_];         // bzp@Wd_z + bd
__device__ float g_Wzo[C_ * L_ * F_];     // Wdz @ Wpm               [64,128]/ch
__device__ float g_Who[C_ * H_ * F_];     // Wd_h @ Wpm              [256,128]/ch
__device__ float g_bo[C_ * F_];           // bdz@Wpm + bpm
__device__ float g_Whh2[C_ * H_ * H_];    // Whh + Wcomb@Wihz        [256,256]/ch
__device__ float g_Wihq[C_ * HX_ * H_];   // Wih_x + Weq@Wihz        [128,256]/ch
__device__ float g_bihq[C_ * H_];         // bih+bhh+bihz + beq@Wihz

// ===========================================================================
// small generic GEMM for weight folding: out = A[M,K]@Bm[K,N] (+ addm)
// addm: optional matrix (ldam) or vector (ldam=0).
// ===========================================================================
__device__ __forceinline__ void small_gemmK(const float* __restrict__ A, int lda,
                                            const float* __restrict__ Bm, int ldb,
                                            float* __restrict__ out, int M, int N,
                                            int K, const float* __restrict__ addm,
                                            int ldam) {
    for (int idx = threadIdx.x; idx < M * N; idx += 256) {
        const int m = idx / N, n = idx % N;
        float s = addm ? addm[(size_t)m * ldam + n] : 0.f;
        const float* a = A + (size_t)m * lda;
        const float* b = Bm + n;
#pragma unroll 4
        for (int k = 0; k < K; ++k) s = fmaf(a[k], b[(size_t)k * ldb], s);
        out[idx] = s;
    }
}

// fold stage 1: products of raw inputs (29 CTAs)
__global__ void __launch_bounds__(256) kernelF1(
    const float* __restrict__ We, const float* __restrict__ be,
    const float* __restrict__ Wqm, const float* __restrict__ bqm,
    const float* __restrict__ Wzp, const float* __restrict__ bzp,
    const float* __restrict__ Wd, const float* __restrict__ bd,
    const float* __restrict__ Wih) {
    const int t = blockIdx.x;
    if (t < 6) {                       // Weq blocks (M=64)
        const int c = t >> 1, rb = t & 1;
        small_gemmK(We + (size_t)c * 384 * EH_ + rb * 64 * EH_, EH_,
                    Wqm + (size_t)c * EH_ * L_, L_,
                    g_Weq + c * HX_ * L_ + rb * 64 * L_, 64, L_, EH_, nullptr, 0);
    } else if (t < 18) {               // Wcomb blocks
        const int u = t - 6, c = u >> 2, rb = u & 3;
        small_gemmK(We + (size_t)c * 384 * EH_ + (128 + rb * 64) * EH_, EH_,
                    Wqm + (size_t)c * EH_ * L_, L_,
                    g_Wcomb + c * H_ * L_ + rb * 64 * L_, 64, L_, EH_, nullptr, 0);
    } else if (t < 21) {               // Wdz = Wzp @ Wd_z
        const int c = t - 18;
        small_gemmK(Wzp, HZ_, Wd + (size_t)c * 384 * EH_, EH_,
                    g_Wdz + c * L_ * EH_, L_, EH_, HZ_, nullptr, 0);
    } else if (t == 21) {              // Wihz = Wzp @ Wih_z
        small_gemmK(Wzp, HZ_, Wih + 128 * H_, H_, g_Wihz, L_, H_, HZ_, nullptr, 0);
    } else if (t < 25) {               // beq = be@Wqm + bqm
        const int c = t - 22;
        small_gemmK(be + c * EH_, EH_, Wqm + (size_t)c * EH_ * L_, L_,
                    g_beq + c * L_, 1, L_, EH_, bqm + c * L_, 0);
    } else if (t < 28) {               // bdz = bzp@Wd_z + bd
        const int c = t - 25;
        small_gemmK(bzp, HZ_, Wd + (size_t)c * 384 * EH_, EH_,
                    g_bdz + c * EH_, 1, EH_, HZ_, bd + c * EH_, 0);
    } else {                           // bihz = bzp@Wih_z
        small_gemmK(bzp, HZ_, Wih + 128 * H_, H_, g_bihz, 1, H_, HZ_, nullptr, 0);
    }
}

// fold stage 2: products involving fold-1 outputs (39 CTAs)
__global__ void __launch_bounds__(256) kernelF2(
    const float* __restrict__ Wd, const float* __restrict__ Wpm,
    const float* __restrict__ bpm, const float* __restrict__ Whh,
    const float* __restrict__ Wih, const float* __restrict__ bih,
    const float* __restrict__ bhh) {
    const int t = blockIdx.x;
    if (t < 3) {                       // Wzo = Wdz @ Wpm
        const int c = t;
        small_gemmK(g_Wdz + c * L_ * EH_, EH_, Wpm + (size_t)c * EH_ * F_, F_,
                    g_Wzo + c * L_ * F_, L_, F_, EH_, nullptr, 0);
    } else if (t < 15) {               // Who = Wd_h @ Wpm
        const int u = t - 3, c = u >> 2, rb = u & 3;
        small_gemmK(Wd + (size_t)c * 384 * EH_ + (128 + rb * 64) * EH_, EH_,
                    Wpm + (size_t)c * EH_ * F_, F_,
                    g_Who + c * H_ * F_ + rb * 64 * F_, 64, F_, EH_, nullptr, 0);
    } else if (t < 18) {               // bo = bdz@Wpm + bpm
        const int c = t - 15;
        small_gemmK(g_bdz + c * EH_, EH_, Wpm + (size_t)c * EH_ * F_, F_,
                    g_bo + c * F_, 1, F_, EH_, bpm + c * F_, 0);
    } else if (t < 30) {               // Whh2 = Whh + Wcomb @ Wihz (K=64)
        const int u = t - 18, c = u >> 2, mb = u & 3;
        small_gemmK(g_Wcomb + c * H_ * L_ + mb * 64 * L_, L_,
                    g_Wihz, H_,
                    g_Whh2 + (size_t)c * H_ * H_ + mb * 64 * H_, 64, H_, L_,
                    Whh + (size_t)mb * 64 * H_, H_);
    } else if (t < 36) {               // Wihq = Wih_x + Weq @ Wihz (K=64)
        const int u = t - 30, c = u >> 1, mb = u & 1;
        small_gemmK(g_Weq + c * HX_ * L_ + mb * 64 * L_, L_,
                    g_Wihz, H_,
                    g_Wihq + (size_t)c * HX_ * H_ + mb * 64 * H_, 64, H_, L_,
                    Wih + (size_t)mb * 64 * H_, H_);
    } else {                           // bihq = bih+bhh+bihz + beq@Wihz
        const int c = t - 36;
        for (int n = threadIdx.x; n < H_; n += 256) {
            float s = bih[n] + bhh[n] + g_bihz[n];
            for (int l = 0; l < L_; ++l)
                s = fmaf(g_beq[c * L_ + l], g_Wihz[l * H_ + n], s);
            g_bihq[c * H_ + n] = s;
        }
    }
}

// ===========================================================================
// Parallel GEMM machinery (kernels A and C)
// ===========================================================================
__device__ __forceinline__ void gemm64(const float* __restrict__ As,
                                       const float* __restrict__ Ws,
                                       int k0, float acc[8][8]) {
    const int tc = threadIdx.x & 15;
    const int tr = threadIdx.x >> 4;
    const float* ap = As + tr * 8 * 128 + k0;
    const float* bp = Ws + tc * 8;
#pragma unroll 4
    for (int k = 0; k < 64; ++k) {
        const float4 b0 = *reinterpret_cast<const float4*>(bp + k * 128);
        const float4 b1 = *reinterpret_cast<const float4*>(bp + k * 128 + 4);
        float a[8];
#pragma unroll
        for (int i = 0; i < 8; ++i) a[i] = ap[i * 128 + k];
        const float bv[8] = {b0.x, b0.y, b0.z, b0.w, b1.x, b1.y, b1.z, b1.w};
#pragma unroll
        for (int i = 0; i < 8; ++i)
#pragma unroll
            for (int j = 0; j < 8; ++j)
                acc[i][j] = fmaf(a[i], bv[j], acc[i][j]);
    }
}

// K=128, N=64 gemm: thread = 4 rows x 8 cols (tr=tid>>3 in 0..31, tc=tid&7)
__device__ __forceinline__ void gemm_K128_N64(const float* __restrict__ As,
                                              const float* __restrict__ Ws,
                                              float acc[4][8]) {
    const int tc = threadIdx.x & 7;
    const int tr = threadIdx.x >> 3;
    const float* ap = As + tr * 4 * 128;
    const float* bp = Ws + tc * 8;
#pragma unroll 4
    for (int k = 0; k < 128; ++k) {
        const float4 b0 = *reinterpret_cast<const float4*>(bp + k * 64);
        const float4 b1 = *reinterpret_cast<const float4*>(bp + k * 64 + 4);
        float a[4];
#pragma unroll
        for (int i = 0; i < 4; ++i) a[i] = ap[i * 128 + k];
        const float bv[8] = {b0.x, b0.y, b0.z, b0.w, b1.x, b1.y, b1.z, b1.w};
#pragma unroll
        for (int i = 0; i < 4; ++i)
#pragma unroll
            for (int j = 0; j < 8; ++j)
                acc[i][j] = fmaf(a[i], bv[j], acc[i][j]);
    }
}

// Load a 128x128 fp32 tile (row stride ld) into smem
__device__ __forceinline__ void load_tile(float* dst, const float* __restrict__ src,
                                          int ld) {
    for (int idx = threadIdx.x; idx < 128 * 32; idx += 256) {
        const int r = idx >> 5;
        const int c4 = idx & 31;
        reinterpret_cast<float4*>(dst)[(r << 5) + c4] =
            *reinterpret_cast<const float4*>(src + (size_t)r * ld + (c4 << 2));
    }
}

// Load a 128x64 tile (contiguous rows of 64) into cols 0..63 of As (stride 128)
__device__ __forceinline__ void load_tile64(float* dst, const float* __restrict__ src) {
    for (int idx = threadIdx.x; idx < 128 * 16; idx += 256) {
        const int r = idx >> 4;
        const int c4 = idx & 15;
        reinterpret_cast<float4*>(dst)[(r << 5) + c4] =
            *reinterpret_cast<const float4*>(src + (size_t)r * 64 + (c4 << 2));
    }
}

// Load a 64x128 fp32 slab (row stride ld) into smem
__device__ __forceinline__ void load_half(float* dst, const float* __restrict__ src,
                                          int ld) {
    for (int idx = threadIdx.x; idx < 64 * 32; idx += 256) {
        const int r = idx >> 5;
        const int c4 = idx & 31;
        reinterpret_cast<float4*>(dst)[(r << 5) + c4] =
            *reinterpret_cast<const float4*>(src + (size_t)r * ld + (c4 << 2));
    }
}

// linear copy of 8192 floats (e.g. full [128,64] or [64,128] weight)
__device__ __forceinline__ void load_lin8k(float* dst, const float* __restrict__ src) {
    for (int idx = threadIdx.x; idx < 2048; idx += 256)
        reinterpret_cast<float4*>(dst)[idx] =
            reinterpret_cast<const float4*>(src)[idx];
}

__device__ __forceinline__ void zero_acc(float acc[8][8]) {
#pragma unroll
    for (int i = 0; i < 8; ++i)
#pragma unroll
        for (int j = 0; j < 8; ++j) acc[i][j] = 0.f;
}

// full 128-deep GEMM as two 64-row slabs streamed through Ws
__device__ __forceinline__ void gemm128_slabs(const float* As, float* Ws,
                                              const float* __restrict__ W,
                                              int ldw, float acc[8][8]) {
#pragma unroll
    for (int h = 0; h < 2; ++h) {
        load_half(Ws, W + (size_t)(h * 64) * ldw, ldw);
        __syncthreads();
        gemm64(As, Ws, h * 64, acc);
        __syncthreads();
    }
}

// ---------------------------------------------------------------------------
// Kernel A: x_phi = x@Wx+bx; PEq = x_phi@Weq + beq; PI = x_phi@Wihq + bihq
// grid (4 btiles, T, C), 256 threads, 96KB dynamic smem
// ---------------------------------------------------------------------------
__global__ void __launch_bounds__(256, 2) kernelA(
    const float* __restrict__ x, const float* __restrict__ Wx,
    const float* __restrict__ bx) {
    extern __shared__ float sm[];
    float* As = sm;                // 128x128
    float* Ws = sm + 128 * 128;    // 8192-float slab
    const int bt = blockIdx.x, t = blockIdx.y, c = blockIdx.z;
    const long rg0 = ((long)(c * T_ + t) * B_ + bt * 128);
    const int tc = threadIdx.x & 15, tr = threadIdx.x >> 4;

    load_tile(As, x + rg0 * F_, F_);

    float acc[8][8];
    zero_acc(acc);
    gemm128_slabs(As, Ws, Wx + (size_t)c * F_ * HX_, HX_, acc);  // x_phi

    // write x_phi (+bx) back into As (trailing sync above protects reads)
#pragma unroll
    for (int i = 0; i < 8; ++i)
#pragma unroll
        for (int j = 0; j < 8; ++j)
            As[(tr * 8 + i) * 128 + tc * 8 + j] = acc[i][j] + bx[c * HX_ + tc * 8 + j];

    // PEq = x_phi @ Weq + beq  (N=64)
    load_lin8k(Ws, g_Weq + c * HX_ * L_);
    __syncthreads();
    {
        float acc4[4][8];
#pragma unroll
        for (int i = 0; i < 4; ++i)
#pragma unroll
            for (int j = 0; j < 8; ++j) acc4[i][j] = 0.f;
        gemm_K128_N64(As, Ws, acc4);
        const int qc = threadIdx.x & 7, qr = threadIdx.x >> 3;
#pragma unroll
        for (int i = 0; i < 4; ++i)
#pragma unroll
            for (int j = 0; j < 8; ++j)
                g_PEq[(rg0 + qr * 4 + i) * L_ + qc * 8 + j] =
                    acc4[i][j] + g_beq[c * L_ + qc * 8 + j];
    }
    __syncthreads();  // protect Ws before PI slabs

    // PI = x_phi @ Wihq + bihq (two 128-col halves)
#pragma unroll
    for (int half = 0; half < 2; ++half) {
        zero_acc(acc);
        gemm128_slabs(As, Ws, g_Wihq + (size_t)c * HX_ * H_ + half * 128, H_, acc);
#pragma unroll
        for (int i = 0; i < 8; ++i)
#pragma unroll
            for (int j = 0; j < 8; ++j) {
                const int n = half * 128 + tc * 8 + j;
                g_PI[(rg0 + tr * 8 + i) * H_ + n] =
                    acc[i][j] + g_bihq[c * H_ + n];
            }
    }
}

// ===========================================================================
// Kernel B: the recurrence (SINGLE fused stage per step, 2 barriers).
// z = PEq + h@Wcomb (for output only); h' = tanh(PI + h@Whh2).
// ===========================================================================
template <int K, int N>
__device__ __forceinline__ void mm4(const float* __restrict__ Wg,
                                    const float* __restrict__ a_s,
                                    float4 acc[RMAX_]) {
    constexpr int G = N / 4;      // thread groups (one per 4 columns)
    constexpr int P = 256 / G;    // k partitions
    constexpr int Ks = K / P;
    const int g = threadIdx.x % G;
    const int p = threadIdx.x / G;
    const float4* wp = reinterpret_cast<const float4*>(Wg) + (size_t)(p * Ks) * G + g;
    const float* ap = a_s + p * Ks;

    float4 w0 = wp[0 * G], w1 = wp[1 * G], w2 = wp[2 * G], w3 = wp[3 * G];
#pragma unroll 1
    for (int k = 0; k < Ks; k += 4) {
        float4 n0, n1, n2, n3;
        if (k + 4 < Ks) {
            n0 = wp[(k + 4) * G];
            n1 = wp[(k + 5) * G];
            n2 = wp[(k + 6) * G];
            n3 = wp[(k + 7) * G];
        }
#pragma unroll
        for (int r = 0; r < RMAX_; ++r) {
            const float4 a = *reinterpret_cast<const float4*>(ap + r * K + k);
            acc[r].x = fmaf(a.x, w0.x, acc[r].x);
            acc[r].y = fmaf(a.x, w0.y, acc[r].y);
            acc[r].z = fmaf(a.x, w0.z, acc[r].z);
            acc[r].w = fmaf(a.x, w0.w, acc[r].w);
            acc[r].x = fmaf(a.y, w1.x, acc[r].x);
            acc[r].y = fmaf(a.y, w1.y, acc[r].y);
            acc[r].z = fmaf(a.y, w1.z, acc[r].z);
            acc[r].w = fmaf(a.y, w1.w, acc[r].w);
            acc[r].x = fmaf(a.z, w2.x, acc[r].x);
            acc[r].y = fmaf(a.z, w2.y, acc[r].y);
            acc[r].z = fmaf(a.z, w2.z, acc[r].z);
            acc[r].w = fmaf(a.z, w2.w, acc[r].w);
            acc[r].x = fmaf(a.w, w3.x, acc[r].x);
            acc[r].y = fmaf(a.w, w3.y, acc[r].y);
            acc[r].z = fmaf(a.w, w3.z, acc[r].z);
            acc[r].w = fmaf(a.w, w3.w, acc[r].w);
        }
        w0 = n0; w1 = n1; w2 = n2; w3 = n3;
    }
}

template <int N>
__device__ __forceinline__ void store_scr(float* __restrict__ scr,
                                          const float4 acc[RMAX_]) {
    const int g = threadIdx.x % (N / 4);
    const int p = threadIdx.x / (N / 4);
#pragma unroll
    for (int r = 0; r < RMAX_; ++r)
        *reinterpret_cast<float4*>(scr + (size_t)(p * RMAX_ + r) * N + 4 * g) = acc[r];
}

__device__ __forceinline__ void zero4(float4 acc[RMAX_]) {
#pragma unroll
    for (int r = 0; r < RMAX_; ++r) acc[r] = make_float4(0.f, 0.f, 0.f, 0.f);
}

__global__ void __launch_bounds__(256, 2) kernelB(const float* __restrict__ h0) {
    // dynamic smem: hs[1536] | scr1[16*6*64=6144] | scr2[4*6*256=6144]
    extern __shared__ float smb[];
    float* hs   = smb;
    float* scr1 = smb + RMAX_ * H_;
    float* scr2 = scr1 + 16 * RMAX_ * 64;

    const int c = blockIdx.y;
    // overlapping coverage: 86 CTAs x 6 rows = 516 >= 512; duplicated rows
    // compute bit-identical values, duplicate global stores are benign.
    const int r0 = (blockIdx.x * (B_ - RMAX_)) / (NB_ - 1);
    const int tid = threadIdx.x;

    for (int idx = tid; idx < RMAX_ * H_; idx += 256)
        hs[idx] = h0[(size_t)(c * B_ + r0) * H_ + idx];
    __syncthreads();

    const float* Wcomb = g_Wcomb + c * H_ * L_;
    const float* Whh2  = g_Whh2 + (size_t)c * H_ * H_;
    float4 acc[RMAX_];

    long rg0 = (long)c * T_ * B_ + r0;
    for (int t = 0; t < T_; ++t, rg0 += B_) {
        // prefetch this step's PEq and PI into registers (overlap with FMAs)
        float pe0 = g_PEq[rg0 * L_ + tid];
        float pe1 = (tid < RMAX_ * L_ - 256) ? g_PEq[rg0 * L_ + 256 + tid] : 0.f;
        float pip[RMAX_];
#pragma unroll
        for (int j = 0; j < RMAX_; ++j)
            pip[j] = g_PI[rg0 * H_ + j * 256 + tid];

        // ---- both GEMMs read only hs: z-part and h-part in one phase
        zero4(acc);
        mm4<256, 64>(Wcomb, hs, acc);      // z partials (P=16)
        store_scr<64>(scr1, acc);
        zero4(acc);
        mm4<256, 256>(Whh2, hs, acc);      // h partials (P=4)
        store_scr<256>(scr2, acc);
        // store Hs[t] = h (pre-update) while partials land
        for (int idx = tid; idx < RMAX_ * H_ / 4; idx += 256)
            reinterpret_cast<float4*>(&g_Hs[rg0 * H_])[idx] =
                reinterpret_cast<const float4*>(hs)[idx];
        __syncthreads();

        // ---- reduce z -> g_Zs (384 outputs)
#pragma unroll
        for (int u = 0; u < 2; ++u) {
            const int idx = u * 256 + tid;
            if (idx < RMAX_ * L_) {
                const int r = idx >> 6, n = idx & 63;
                float s = u == 0 ? pe0 : pe1;
#pragma unroll
                for (int p = 0; p < 16; ++p)
                    s += scr1[(size_t)(p * RMAX_ + r) * 64 + n];
                g_Zs[rg0 * L_ + idx] = s;
            }
        }
        // ---- reduce h -> tanh -> hs (1536 outputs)
#pragma unroll
        for (int j = 0; j < RMAX_; ++j) {
            const int idx = j * 256 + tid;
            const int r = idx >> 8;
            const int n = idx & 255;
            float s = pip[j];
#pragma unroll
            for (int p = 0; p < 4; ++p)
                s += scr2[(size_t)(p * RMAX_ + r) * 256 + n];
            hs[idx] = tanhf(s);
        }
        __syncthreads();
    }
}

// ---------------------------------------------------------------------------
// Kernel C: out = Zs@Wzo + Hs@Who + bo
// grid (4 btiles, T, C), 256 threads, 96KB dynamic smem
// ---------------------------------------------------------------------------
__global__ void __launch_bounds__(256, 2) kernelC(float* __restrict__ out) {
    extern __shared__ float sm[];
    float* As = sm;
    float* Ws = sm + 128 * 128;
    const int bt = blockIdx.x, t = blockIdx.y, c = blockIdx.z;
    const long rg0 = ((long)(c * T_ + t) * B_ + bt * 128);
    const int tc = threadIdx.x & 15, tr = threadIdx.x >> 4;

    float acc[8][8];
    zero_acc(acc);

    // h part: two 128-row slices of Who (K=256 total)
    load_tile(As, g_Hs + rg0 * H_, H_);
    gemm128_slabs(As, Ws, g_Who + (size_t)c * H_ * F_, F_, acc);
    load_tile(As, g_Hs + rg0 * H_ + 128, H_);
    gemm128_slabs(As, Ws, g_Who + (size_t)c * H_ * F_ + 128 * F_, F_, acc);

    // z part: K=64
    load_tile64(As, g_Zs + rg0 * L_);
    load_lin8k(Ws, g_Wzo + c * L_ * F_);   // [64,128]
    __syncthreads();
    gemm64(As, Ws, 0, acc);

#pragma unroll
    for (int i = 0; i < 8; ++i)
#pragma unroll
        for (int j = 0; j < 8; ++j)
            out[(rg0 + tr * 8 + i) * F_ + tc * 8 + j] =
                acc[i][j] + g_bo[c * F_ + tc * 8 + j];
}

// ---------------------------------------------------------------------------
extern "C" void kernel_launch(void* const* d_in, const int* in_sizes, int n_in,
                              void* d_out, int out_size) {
    (void)in_sizes; (void)n_in; (void)out_size;
    const float* x        = (const float*)d_in[0];
    const float* phi_x_W  = (const float*)d_in[1];
    const float* phi_x_b  = (const float*)d_in[2];
    const float* enc_W    = (const float*)d_in[3];
    const float* enc_b    = (const float*)d_in[4];
    const float* enc_mu_W = (const float*)d_in[5];
    const float* enc_mu_b = (const float*)d_in[6];
    const float* phi_z_W  = (const float*)d_in[7];
    const float* phi_z_b  = (const float*)d_in[8];
    const float* dec_W    = (const float*)d_in[9];
    const float* dec_b    = (const float*)d_in[10];
    const float* dec_mu_W = (const float*)d_in[11];
    const float* dec_mu_b = (const float*)d_in[12];
    const float* rnn_Wih  = (const float*)d_in[13];
    const float* rnn_Whh  = (const float*)d_in[14];
    const float* rnn_bih  = (const float*)d_in[15];
    const float* rnn_bhh  = (const float*)d_in[16];
    const float* h0       = (const float*)d_in[17];
    float* out = (float*)d_out;

    const size_t smemAC = (128 * 128 + 64 * 128) * sizeof(float);  // 96 KB
    const size_t smemB  = (RMAX_ * H_ + 16 * RMAX_ * 64 + 4 * RMAX_ * 256)
                          * sizeof(float);                          // ~54 KB
    cudaFuncSetAttribute(kernelA, cudaFuncAttributeMaxDynamicSharedMemorySize,
                         (int)smemAC);
    cudaFuncSetAttribute(kernelB, cudaFuncAttributeMaxDynamicSharedMemorySize,
                         (int)smemB);
    cudaFuncSetAttribute(kernelC, cudaFuncAttributeMaxDynamicSharedMemorySize,
                         (int)smemAC);

    kernelF1<<<29, 256>>>(enc_W, enc_b, enc_mu_W, enc_mu_b, phi_z_W, phi_z_b,
                          dec_W, dec_b, rnn_Wih);
    kernelF2<<<39, 256>>>(dec_W, dec_mu_W, dec_mu_b, rnn_Whh, rnn_Wih,
                          rnn_bih, rnn_bhh);
    kernelA<<<dim3(4, T_, C_), 256, smemAC>>>(x, phi_x_W, phi_x_b);
    kernelB<<<dim3(NB_, C_), 256, smemB>>>(h0);
    kernelC<<<dim3(4, T_, C_), 256, smemAC>>>(out);
}

// round 8
// speedup vs baseline: 1.4075x; 1.0557x over previous
#include <cuda_runtime.h>
#include <math.h>

// Problem dims
#define C_   3
#define T_   100
#define B_   512
#define F_   128
#define HX_  128
#define HZ_  128
#define H_   256
#define EH_  128
#define L_   64

#define NB_   86   // CTAs per channel (86*6=516 >= 512; 258 CTAs, 1 wave @ 2/SM)
#define RMAX_ 6    // rows per CTA

// ---- big activations scratch ----
__device__ float g_PI[(size_t)C_ * T_ * B_ * H_];   // x_phi@Wihq + bihq
__device__ float g_PO[(size_t)C_ * T_ * B_ * F_];   // x_phi@Wxo + bo2
__device__ float g_Hs[(size_t)C_ * T_ * B_ * H_];   // h at step input

// ---- folded weights (computed on-device each run; tiny) ----
__device__ float g_Weq[C_ * HX_ * L_];    // We_x @ Wqm              [128,64]/ch
__device__ float g_beq[C_ * L_];          // be@Wqm + bqm
__device__ float g_Wcomb[C_ * H_ * L_];   // We_h @ Wqm              [256,64]/ch
__device__ float g_Wihz[L_ * H_];         // Wzp @ Wih_z             [64,256]
__device__ float g_bihz[H_];              // bzp @ Wih_z
__device__ float g_Wdz[C_ * L_ * EH_];    // Wzp @ Wd_z              [64,128]/ch
__device__ float g_bdz[C_ * EH_];         // bzp@Wd_z + bd
__device__ float g_Wzo[C_ * L_ * F_];     // Wdz @ Wpm               [64,128]/ch
__device__ float g_Who[C_ * H_ * F_];     // Wd_h @ Wpm              [256,128]/ch
__device__ float g_bo[C_ * F_];           // bdz@Wpm + bpm
__device__ float g_Whh2[C_ * H_ * H_];    // Whh + Wcomb@Wihz        [256,256]/ch
__device__ float g_Wihq[C_ * HX_ * H_];   // Wih_x + Weq@Wihz        [128,256]/ch
__device__ float g_bihq[C_ * H_];         // bih+bhh+bihz + beq@Wihz
__device__ float g_Who2[C_ * H_ * F_];    // Who + Wcomb@Wzo         [256,128]/ch
__device__ float g_Wxo[C_ * HX_ * F_];    // Weq @ Wzo               [128,128]/ch
__device__ float g_bo2[C_ * F_];          // beq@Wzo + bo

// ===========================================================================
// small generic GEMM for weight folding: out = A[M,K]@Bm[K,N] (+ addm)
// ===========================================================================
__device__ __forceinline__ void small_gemmK(const float* __restrict__ A, int lda,
                                            const float* __restrict__ Bm, int ldb,
                                            float* __restrict__ out, int M, int N,
                                            int K, const float* __restrict__ addm,
                                            int ldam) {
    for (int idx = threadIdx.x; idx < M * N; idx += 256) {
        const int m = idx / N, n = idx % N;
        float s = addm ? addm[(size_t)m * ldam + n] : 0.f;
        const float* a = A + (size_t)m * lda;
        const float* b = Bm + n;
#pragma unroll 4
        for (int k = 0; k < K; ++k) s = fmaf(a[k], b[(size_t)k * ldb], s);
        out[idx] = s;
    }
}

// fold stage 1: products of raw inputs (29 CTAs)
__global__ void __launch_bounds__(256) kernelF1(
    const float* __restrict__ We, const float* __restrict__ be,
    const float* __restrict__ Wqm, const float* __restrict__ bqm,
    const float* __restrict__ Wzp, const float* __restrict__ bzp,
    const float* __restrict__ Wd, const float* __restrict__ bd,
    const float* __restrict__ Wih) {
    const int t = blockIdx.x;
    if (t < 6) {                       // Weq blocks (M=64)
        const int c = t >> 1, rb = t & 1;
        small_gemmK(We + (size_t)c * 384 * EH_ + rb * 64 * EH_, EH_,
                    Wqm + (size_t)c * EH_ * L_, L_,
                    g_Weq + c * HX_ * L_ + rb * 64 * L_, 64, L_, EH_, nullptr, 0);
    } else if (t < 18) {               // Wcomb blocks
        const int u = t - 6, c = u >> 2, rb = u & 3;
        small_gemmK(We + (size_t)c * 384 * EH_ + (128 + rb * 64) * EH_, EH_,
                    Wqm + (size_t)c * EH_ * L_, L_,
                    g_Wcomb + c * H_ * L_ + rb * 64 * L_, 64, L_, EH_, nullptr, 0);
    } else if (t < 21) {               // Wdz = Wzp @ Wd_z
        const int c = t - 18;
        small_gemmK(Wzp, HZ_, Wd + (size_t)c * 384 * EH_, EH_,
                    g_Wdz + c * L_ * EH_, L_, EH_, HZ_, nullptr, 0);
    } else if (t == 21) {              // Wihz = Wzp @ Wih_z
        small_gemmK(Wzp, HZ_, Wih + 128 * H_, H_, g_Wihz, L_, H_, HZ_, nullptr, 0);
    } else if (t < 25) {               // beq = be@Wqm + bqm
        const int c = t - 22;
        small_gemmK(be + c * EH_, EH_, Wqm + (size_t)c * EH_ * L_, L_,
                    g_beq + c * L_, 1, L_, EH_, bqm + c * L_, 0);
    } else if (t < 28) {               // bdz = bzp@Wd_z + bd
        const int c = t - 25;
        small_gemmK(bzp, HZ_, Wd + (size_t)c * 384 * EH_, EH_,
                    g_bdz + c * EH_, 1, EH_, HZ_, bd + c * EH_, 0);
    } else {                           // bihz = bzp@Wih_z
        small_gemmK(bzp, HZ_, Wih + 128 * H_, H_, g_bihz, 1, H_, HZ_, nullptr, 0);
    }
}

// fold stage 2: products involving fold-1 outputs (39 CTAs)
__global__ void __launch_bounds__(256) kernelF2(
    const float* __restrict__ Wd, const float* __restrict__ Wpm,
    const float* __restrict__ bpm, const float* __restrict__ Whh,
    const float* __restrict__ Wih, const float* __restrict__ bih,
    const float* __restrict__ bhh) {
    const int t = blockIdx.x;
    if (t < 3) {                       // Wzo = Wdz @ Wpm
        const int c = t;
        small_gemmK(g_Wdz + c * L_ * EH_, EH_, Wpm + (size_t)c * EH_ * F_, F_,
                    g_Wzo + c * L_ * F_, L_, F_, EH_, nullptr, 0);
    } else if (t < 15) {               // Who = Wd_h @ Wpm
        const int u = t - 3, c = u >> 2, rb = u & 3;
        small_gemmK(Wd + (size_t)c * 384 * EH_ + (128 + rb * 64) * EH_, EH_,
                    Wpm + (size_t)c * EH_ * F_, F_,
                    g_Who + c * H_ * F_ + rb * 64 * F_, 64, F_, EH_, nullptr, 0);
    } else if (t < 18) {               // bo = bdz@Wpm + bpm
        const int c = t - 15;
        small_gemmK(g_bdz + c * EH_, EH_, Wpm + (size_t)c * EH_ * F_, F_,
                    g_bo + c * F_, 1, F_, EH_, bpm + c * F_, 0);
    } else if (t < 30) {               // Whh2 = Whh + Wcomb @ Wihz (K=64)
        const int u = t - 18, c = u >> 2, mb = u & 3;
        small_gemmK(g_Wcomb + c * H_ * L_ + mb * 64 * L_, L_,
                    g_Wihz, H_,
                    g_Whh2 + (size_t)c * H_ * H_ + mb * 64 * H_, 64, H_, L_,
                    Whh + (size_t)mb * 64 * H_, H_);
    } else if (t < 36) {               // Wihq = Wih_x + Weq @ Wihz (K=64)
        const int u = t - 30, c = u >> 1, mb = u & 1;
        small_gemmK(g_Weq + c * HX_ * L_ + mb * 64 * L_, L_,
                    g_Wihz, H_,
                    g_Wihq + (size_t)c * HX_ * H_ + mb * 64 * H_, 64, H_, L_,
                    Wih + (size_t)mb * 64 * H_, H_);
    } else {                           // bihq = bih+bhh+bihz + beq@Wihz
        const int c = t - 36;
        for (int n = threadIdx.x; n < H_; n += 256) {
            float s = bih[n] + bhh[n] + g_bihz[n];
            for (int l = 0; l < L_; ++l)
                s = fmaf(g_beq[c * L_ + l], g_Wihz[l * H_ + n], s);
            g_bihq[c * H_ + n] = s;
        }
    }
}

// fold stage 3: output-path folds (21 CTAs)
__global__ void __launch_bounds__(256) kernelF3() {
    const int t = blockIdx.x;
    if (t < 12) {                      // Who2 = Who + Wcomb @ Wzo (K=64)
        const int c = t >> 2, mb = t & 3;
        small_gemmK(g_Wcomb + c * H_ * L_ + mb * 64 * L_, L_,
                    g_Wzo + c * L_ * F_, F_,
                    g_Who2 + c * H_ * F_ + mb * 64 * F_, 64, F_, L_,
                    g_Who + c * H_ * F_ + mb * 64 * F_, F_);
    } else if (t < 18) {               // Wxo = Weq @ Wzo (K=64)
        const int u = t - 12, c = u >> 1, mb = u & 1;
        small_gemmK(g_Weq + c * HX_ * L_ + mb * 64 * L_, L_,
                    g_Wzo + c * L_ * F_, F_,
                    g_Wxo + c * HX_ * F_ + mb * 64 * F_, 64, F_, L_, nullptr, 0);
    } else {                           // bo2 = beq@Wzo + bo
        const int c = t - 18;
        small_gemmK(g_beq + c * L_, L_, g_Wzo + c * L_ * F_, F_,
                    g_bo2 + c * F_, 1, F_, L_, g_bo + c * F_, 0);
    }
}

// ===========================================================================
// Parallel GEMM machinery (kernels A and C)
// ===========================================================================
__device__ __forceinline__ void gemm64(const float* __restrict__ As,
                                       const float* __restrict__ Ws,
                                       int k0, float acc[8][8]) {
    const int tc = threadIdx.x & 15;
    const int tr = threadIdx.x >> 4;
    const float* ap = As + tr * 8 * 128 + k0;
    const float* bp = Ws + tc * 8;
#pragma unroll 4
    for (int k = 0; k < 64; ++k) {
        const float4 b0 = *reinterpret_cast<const float4*>(bp + k * 128);
        const float4 b1 = *reinterpret_cast<const float4*>(bp + k * 128 + 4);
        float a[8];
#pragma unroll
        for (int i = 0; i < 8; ++i) a[i] = ap[i * 128 + k];
        const float bv[8] = {b0.x, b0.y, b0.z, b0.w, b1.x, b1.y, b1.z, b1.w};
#pragma unroll
        for (int i = 0; i < 8; ++i)
#pragma unroll
            for (int j = 0; j < 8; ++j)
                acc[i][j] = fmaf(a[i], bv[j], acc[i][j]);
    }
}

// Load a 128x128 fp32 tile (row stride ld) into smem
__device__ __forceinline__ void load_tile(float* dst, const float* __restrict__ src,
                                          int ld) {
    for (int idx = threadIdx.x; idx < 128 * 32; idx += 256) {
        const int r = idx >> 5;
        const int c4 = idx & 31;
        reinterpret_cast<float4*>(dst)[(r << 5) + c4] =
            *reinterpret_cast<const float4*>(src + (size_t)r * ld + (c4 << 2));
    }
}

// Load a 64x128 fp32 slab (row stride ld) into smem
__device__ __forceinline__ void load_half(float* dst, const float* __restrict__ src,
                                          int ld) {
    for (int idx = threadIdx.x; idx < 64 * 32; idx += 256) {
        const int r = idx >> 5;
        const int c4 = idx & 31;
        reinterpret_cast<float4*>(dst)[(r << 5) + c4] =
            *reinterpret_cast<const float4*>(src + (size_t)r * ld + (c4 << 2));
    }
}

__device__ __forceinline__ void zero_acc(float acc[8][8]) {
#pragma unroll
    for (int i = 0; i < 8; ++i)
#pragma unroll
        for (int j = 0; j < 8; ++j) acc[i][j] = 0.f;
}

// full 128-deep GEMM as two 64-row slabs streamed through Ws
__device__ __forceinline__ void gemm128_slabs(const float* As, float* Ws,
                                              const float* __restrict__ W,
                                              int ldw, float acc[8][8]) {
#pragma unroll
    for (int h = 0; h < 2; ++h) {
        load_half(Ws, W + (size_t)(h * 64) * ldw, ldw);
        __syncthreads();
        gemm64(As, Ws, h * 64, acc);
        __syncthreads();
    }
}

// ---------------------------------------------------------------------------
// Kernel A: x_phi = x@Wx+bx; PO = x_phi@Wxo + bo2; PI = x_phi@Wihq + bihq
// grid (4 btiles, T, C), 256 threads, 96KB dynamic smem
// ---------------------------------------------------------------------------
__global__ void __launch_bounds__(256, 2) kernelA(
    const float* __restrict__ x, const float* __restrict__ Wx,
    const float* __restrict__ bx) {
    extern __shared__ float sm[];
    float* As = sm;                // 128x128
    float* Ws = sm + 128 * 128;    // 8192-float slab
    const int bt = blockIdx.x, t = blockIdx.y, c = blockIdx.z;
    const long rg0 = ((long)(c * T_ + t) * B_ + bt * 128);
    const int tc = threadIdx.x & 15, tr = threadIdx.x >> 4;

    load_tile(As, x + rg0 * F_, F_);

    float acc[8][8];
    zero_acc(acc);
    gemm128_slabs(As, Ws, Wx + (size_t)c * F_ * HX_, HX_, acc);  // x_phi

    // write x_phi (+bx) back into As (next sync in gemm128_slabs orders reads)
#pragma unroll
    for (int i = 0; i < 8; ++i)
#pragma unroll
        for (int j = 0; j < 8; ++j)
            As[(tr * 8 + i) * 128 + tc * 8 + j] = acc[i][j] + bx[c * HX_ + tc * 8 + j];

    // PO = x_phi @ Wxo + bo2
    zero_acc(acc);
    gemm128_slabs(As, Ws, g_Wxo + (size_t)c * HX_ * F_, F_, acc);
#pragma unroll
    for (int i = 0; i < 8; ++i)
#pragma unroll
        for (int j = 0; j < 8; ++j)
            g_PO[(rg0 + tr * 8 + i) * F_ + tc * 8 + j] =
                acc[i][j] + g_bo2[c * F_ + tc * 8 + j];

    // PI = x_phi @ Wihq + bihq (two 128-col halves)
#pragma unroll
    for (int half = 0; half < 2; ++half) {
        zero_acc(acc);
        gemm128_slabs(As, Ws, g_Wihq + (size_t)c * HX_ * H_ + half * 128, H_, acc);
#pragma unroll
        for (int i = 0; i < 8; ++i)
#pragma unroll
            for (int j = 0; j < 8; ++j) {
                const int n = half * 128 + tc * 8 + j;
                g_PI[(rg0 + tr * 8 + i) * H_ + n] =
                    acc[i][j] + g_bihq[c * H_ + n];
            }
    }
}

// ===========================================================================
// Kernel B: the pure recurrence: h' = tanh(PI + h@Whh2). One GEMM per step.
// ===========================================================================
template <int K, int N>
__device__ __forceinline__ void mm4(const float* __restrict__ Wg,
                                    const float* __restrict__ a_s,
                                    float4 acc[RMAX_]) {
    constexpr int G = N / 4;      // thread groups (one per 4 columns)
    constexpr int P = 256 / G;    // k partitions
    constexpr int Ks = K / P;
    const int g = threadIdx.x % G;
    const int p = threadIdx.x / G;
    const float4* wp = reinterpret_cast<const float4*>(Wg) + (size_t)(p * Ks) * G + g;
    const float* ap = a_s + p * Ks;

    float4 w0 = wp[0 * G], w1 = wp[1 * G], w2 = wp[2 * G], w3 = wp[3 * G];
#pragma unroll 1
    for (int k = 0; k < Ks; k += 4) {
        float4 n0, n1, n2, n3;
        if (k + 4 < Ks) {
            n0 = wp[(k + 4) * G];
            n1 = wp[(k + 5) * G];
            n2 = wp[(k + 6) * G];
            n3 = wp[(k + 7) * G];
        }
#pragma unroll
        for (int r = 0; r < RMAX_; ++r) {
            const float4 a = *reinterpret_cast<const float4*>(ap + r * K + k);
            acc[r].x = fmaf(a.x, w0.x, acc[r].x);
            acc[r].y = fmaf(a.x, w0.y, acc[r].y);
            acc[r].z = fmaf(a.x, w0.z, acc[r].z);
            acc[r].w = fmaf(a.x, w0.w, acc[r].w);
            acc[r].x = fmaf(a.y, w1.x, acc[r].x);
            acc[r].y = fmaf(a.y, w1.y, acc[r].y);
            acc[r].z = fmaf(a.y, w1.z, acc[r].z);
            acc[r].w = fmaf(a.y, w1.w, acc[r].w);
            acc[r].x = fmaf(a.z, w2.x, acc[r].x);
            acc[r].y = fmaf(a.z, w2.y, acc[r].y);
            acc[r].z = fmaf(a.z, w2.z, acc[r].z);
            acc[r].w = fmaf(a.z, w2.w, acc[r].w);
            acc[r].x = fmaf(a.w, w3.x, acc[r].x);
            acc[r].y = fmaf(a.w, w3.y, acc[r].y);
            acc[r].z = fmaf(a.w, w3.z, acc[r].z);
            acc[r].w = fmaf(a.w, w3.w, acc[r].w);
        }
        w0 = n0; w1 = n1; w2 = n2; w3 = n3;
    }
}

template <int N>
__device__ __forceinline__ void store_scr(float* __restrict__ scr,
                                          const float4 acc[RMAX_]) {
    const int g = threadIdx.x % (N / 4);
    const int p = threadIdx.x / (N / 4);
#pragma unroll
    for (int r = 0; r < RMAX_; ++r)
        *reinterpret_cast<float4*>(scr + (size_t)(p * RMAX_ + r) * N + 4 * g) = acc[r];
}

__device__ __forceinline__ void zero4(float4 acc[RMAX_]) {
#pragma unroll
    for (int r = 0; r < RMAX_; ++r) acc[r] = make_float4(0.f, 0.f, 0.f, 0.f);
}

__global__ void __launch_bounds__(256, 2) kernelB(const float* __restrict__ h0) {
    // dynamic smem: hs[1536] | scr2[4*6*256=6144]  -> 30 KB
    extern __shared__ float smb[];
    float* hs   = smb;
    float* scr2 = smb + RMAX_ * H_;

    const int c = blockIdx.y;
    // overlapping coverage: 86 CTAs x 6 rows = 516 >= 512; duplicated rows
    // compute bit-identical values, duplicate global stores are benign.
    const int r0 = (blockIdx.x * (B_ - RMAX_)) / (NB_ - 1);
    const int tid = threadIdx.x;

    for (int idx = tid; idx < RMAX_ * H_; idx += 256)
        hs[idx] = h0[(size_t)(c * B_ + r0) * H_ + idx];
    __syncthreads();

    const float* Whh2 = g_Whh2 + (size_t)c * H_ * H_;
    float4 acc[RMAX_];

    long rg0 = (long)c * T_ * B_ + r0;
    for (int t = 0; t < T_; ++t, rg0 += B_) {
        // prefetch this step's PI into registers (overlaps with FMAs below)
        float pip[RMAX_];
#pragma unroll
        for (int j = 0; j < RMAX_; ++j)
            pip[j] = g_PI[rg0 * H_ + j * 256 + tid];

        zero4(acc);
        mm4<256, 256>(Whh2, hs, acc);      // h partials (P=4)
        store_scr<256>(scr2, acc);
        // store Hs[t] = h (pre-update) while partials land
        for (int idx = tid; idx < RMAX_ * H_ / 4; idx += 256)
            reinterpret_cast<float4*>(&g_Hs[rg0 * H_])[idx] =
                reinterpret_cast<const float4*>(hs)[idx];
        __syncthreads();

        // reduce 4 partials + PI -> tanh -> hs (1536 outputs)
#pragma unroll
        for (int j = 0; j < RMAX_; ++j) {
            const int idx = j * 256 + tid;
            const int r = idx >> 8;
            const int n = idx & 255;
            float s = pip[j];
#pragma unroll
            for (int p = 0; p < 4; ++p)
                s += scr2[(size_t)(p * RMAX_ + r) * 256 + n];
            hs[idx] = tanhf(s);
        }
        __syncthreads();
    }
}

// ---------------------------------------------------------------------------
// Kernel C: out = PO + Hs@Who2
// grid (4 btiles, T, C), 256 threads, 96KB dynamic smem
// ---------------------------------------------------------------------------
__global__ void __launch_bounds__(256, 2) kernelC(float* __restrict__ out) {
    extern __shared__ float sm[];
    float* As = sm;
    float* Ws = sm + 128 * 128;
    const int bt = blockIdx.x, t = blockIdx.y, c = blockIdx.z;
    const long rg0 = ((long)(c * T_ + t) * B_ + bt * 128);
    const int tc = threadIdx.x & 15, tr = threadIdx.x >> 4;

    float acc[8][8];
    zero_acc(acc);

    // h part: two 128-row slices of Who2 (K=256 total)
    load_tile(As, g_Hs + rg0 * H_, H_);
    gemm128_slabs(As, Ws, g_Who2 + (size_t)c * H_ * F_, F_, acc);
    load_tile(As, g_Hs + rg0 * H_ + 128, H_);
    gemm128_slabs(As, Ws, g_Who2 + (size_t)c * H_ * F_ + 128 * F_, F_, acc);

#pragma unroll
    for (int i = 0; i < 8; ++i)
#pragma unroll
        for (int j = 0; j < 8; ++j) {
            const long o = (rg0 + tr * 8 + i) * F_ + tc * 8 + j;
            out[o] = acc[i][j] + g_PO[o];
        }
}

// ---------------------------------------------------------------------------
extern "C" void kernel_launch(void* const* d_in, const int* in_sizes, int n_in,
                              void* d_out, int out_size) {
    (void)in_sizes; (void)n_in; (void)out_size;
    const float* x        = (const float*)d_in[0];
    const float* phi_x_W  = (const float*)d_in[1];
    const float* phi_x_b  = (const float*)d_in[2];
    const float* enc_W    = (const float*)d_in[3];
    const float* enc_b    = (const float*)d_in[4];
    const float* enc_mu_W = (const float*)d_in[5];
    const float* enc_mu_b = (const float*)d_in[6];
    const float* phi_z_W  = (const float*)d_in[7];
    const float* phi_z_b  = (const float*)d_in[8];
    const float* dec_W    = (const float*)d_in[9];
    const float* dec_b    = (const float*)d_in[10];
    const float* dec_mu_W = (const float*)d_in[11];
    const float* dec_mu_b = (const float*)d_in[12];
    const float* rnn_Wih  = (const float*)d_in[13];
    const float* rnn_Whh  = (const float*)d_in[14];
    const float* rnn_bih  = (const float*)d_in[15];
    const float* rnn_bhh  = (const float*)d_in[16];
    const float* h0       = (const float*)d_in[17];
    float* out = (float*)d_out;

    const size_t smemAC = (128 * 128 + 64 * 128) * sizeof(float);  // 96 KB
    const size_t smemB  = (RMAX_ * H_ + 4 * RMAX_ * 256) * sizeof(float); // 30 KB
    cudaFuncSetAttribute(kernelA, cudaFuncAttributeMaxDynamicSharedMemorySize,
                         (int)smemAC);
    cudaFuncSetAttribute(kernelB, cudaFuncAttributeMaxDynamicSharedMemorySize,
                         (int)smemB);
    cudaFuncSetAttribute(kernelC, cudaFuncAttributeMaxDynamicSharedMemorySize,
                         (int)smemAC);

    kernelF1<<<29, 256>>>(enc_W, enc_b, enc_mu_W, enc_mu_b, phi_z_W, phi_z_b,
                          dec_W, dec_b, rnn_Wih);
    kernelF2<<<39, 256>>>(dec_W, dec_mu_W, dec_mu_b, rnn_Whh, rnn_Wih,
                          rnn_bih, rnn_bhh);
    kernelF3<<<21, 256>>>();
    kernelA<<<dim3(4, T_, C_), 256, smemAC>>>(x, phi_x_W, phi_x_b);
    kernelB<<<dim3(NB_, C_), 256, smemB>>>(h0);
    kernelC<<<dim3(4, T_, C_), 256, smemAC>>>(out);
}